// round 3
// baseline (speedup 1.0000x reference)
#include <cuda_runtime.h>
#include <cuda_bf16.h>
#include <cstdint>

#define BSZ     128
#define DTOT    196608          // 3*256*256
#define KSTAGE  32
#define CHUNK   1344            // 42 stages of 32
#define NBLK    147             // ceil(196608/1344)
#define REGW    0.01f
#define NUM_SINK 32
#define LOG_AB  (-4.852030263919617f)   // log(1/128)

// -------- device scratch (static: no allocations allowed) --------
__device__ float g_part[NBLK][BSZ * BSZ];   // per-block GEMM partials (~9.6 MB)
__device__ float g_x2p[NBLK][BSZ];
__device__ float g_y2p[NBLK][BSZ];
__device__ float g_C[BSZ * BSZ];

__device__ __forceinline__ unsigned smem_u32(const void* p) {
    return (unsigned)__cvta_generic_to_shared(p);
}

#define MMA_BF16(d, A, bx, by)                                                  \
    asm volatile("mma.sync.aligned.m16n8k16.row.col.f32.bf16.bf16.f32 "         \
                 "{%0,%1,%2,%3}, {%4,%5,%6,%7}, {%8,%9}, {%0,%1,%2,%3};"        \
                 : "+f"(d[0]), "+f"(d[1]), "+f"(d[2]), "+f"(d[3])               \
                 : "r"(A[0]), "r"(A[1]), "r"(A[2]), "r"(A[3]), "r"(bx), "r"(by))

#define LDSM_X4(r, p)                                                           \
    asm volatile("ldmatrix.sync.aligned.m8n8.x4.shared.b16 {%0,%1,%2,%3}, [%4];"\
                 : "=r"(r[0]), "=r"(r[1]), "=r"(r[2]), "=r"(r[3])               \
                 : "r"(smem_u32(p)))

// =====================================================================
// Kernel A: split-K bf16 GEMM of Delta @ Target^T, plus fp32 row norms.
// Grid: NBLK blocks, each handles a K-chunk of up to CHUNK columns.
// =====================================================================
__global__ void __launch_bounds__(512, 1)
gemm_kernel(const float* __restrict__ gi,   // imgs
            const float* __restrict__ gw,   // imgs_w
            const float* __restrict__ gt)   // target
{
    __shared__ __nv_bfloat16 As[2][128][40];   // delta tile, padded stride 40
    __shared__ __nv_bfloat16 Bs[2][128][40];   // target tile

    const int t      = threadIdx.x;
    const int blk    = blockIdx.x;
    const int k0     = blk * CHUNK;
    const int kcount = min(CHUNK, DTOT - k0);
    const int nstages = kcount / KSTAGE;

    const int lane = t & 31;
    const int warp = t >> 5;
    const int wm   = (warp >> 2) * 32;    // output row base of this warp
    const int wn   = (warp & 3) * 32;     // output col base

    float acc[2][4][4];
#pragma unroll
    for (int a = 0; a < 2; ++a)
#pragma unroll
        for (int b = 0; b < 4; ++b)
#pragma unroll
            for (int r = 0; r < 4; ++r) acc[a][b][r] = 0.f;

    const int row0 = t >> 3;          // 0..63
    const int cseg = (t & 7) * 4;     // float offset within 32-wide stage

    const size_t off0 = (size_t)row0 * DTOT + k0 + cseg;
    const size_t off1 = (size_t)(row0 + 64) * DTOT + k0 + cseg;

    float4 ri0, ri1, rw0, rw1, rt0, rt1;
    float x2a = 0.f, x2b = 0.f, y2a = 0.f, y2b = 0.f;

    // prefetch stage 0
    ri0 = *(const float4*)(gi + off0);
    ri1 = *(const float4*)(gi + off1);
    rw0 = *(const float4*)(gw + off0);
    rw1 = *(const float4*)(gw + off1);
    rt0 = *(const float4*)(gt + off0);
    rt1 = *(const float4*)(gt + off1);

    for (int s = 0; s < nstages; ++s) {
        const int buf = s & 1;

        float4 d0, d1;
        d0.x = rw0.x - ri0.x; d0.y = rw0.y - ri0.y;
        d0.z = rw0.z - ri0.z; d0.w = rw0.w - ri0.w;
        d1.x = rw1.x - ri1.x; d1.y = rw1.y - ri1.y;
        d1.z = rw1.z - ri1.z; d1.w = rw1.w - ri1.w;

        x2a += d0.x*d0.x + d0.y*d0.y + d0.z*d0.z + d0.w*d0.w;
        x2b += d1.x*d1.x + d1.y*d1.y + d1.z*d1.z + d1.w*d1.w;
        y2a += rt0.x*rt0.x + rt0.y*rt0.y + rt0.z*rt0.z + rt0.w*rt0.w;
        y2b += rt1.x*rt1.x + rt1.y*rt1.y + rt1.z*rt1.z + rt1.w*rt1.w;

        *(__nv_bfloat162*)&As[buf][row0][cseg + 0]      = __float22bfloat162_rn(make_float2(d0.x, d0.y));
        *(__nv_bfloat162*)&As[buf][row0][cseg + 2]      = __float22bfloat162_rn(make_float2(d0.z, d0.w));
        *(__nv_bfloat162*)&As[buf][row0 + 64][cseg + 0] = __float22bfloat162_rn(make_float2(d1.x, d1.y));
        *(__nv_bfloat162*)&As[buf][row0 + 64][cseg + 2] = __float22bfloat162_rn(make_float2(d1.z, d1.w));
        *(__nv_bfloat162*)&Bs[buf][row0][cseg + 0]      = __float22bfloat162_rn(make_float2(rt0.x, rt0.y));
        *(__nv_bfloat162*)&Bs[buf][row0][cseg + 2]      = __float22bfloat162_rn(make_float2(rt0.z, rt0.w));
        *(__nv_bfloat162*)&Bs[buf][row0 + 64][cseg + 0] = __float22bfloat162_rn(make_float2(rt1.x, rt1.y));
        *(__nv_bfloat162*)&Bs[buf][row0 + 64][cseg + 2] = __float22bfloat162_rn(make_float2(rt1.z, rt1.w));

        __syncthreads();

        // prefetch next stage while tensor cores run
        if (s + 1 < nstages) {
            const size_t adv = (size_t)(s + 1) * KSTAGE;
            ri0 = *(const float4*)(gi + off0 + adv);
            ri1 = *(const float4*)(gi + off1 + adv);
            rw0 = *(const float4*)(gw + off0 + adv);
            rw1 = *(const float4*)(gw + off1 + adv);
            rt0 = *(const float4*)(gt + off0 + adv);
            rt1 = *(const float4*)(gt + off1 + adv);
        }

#pragma unroll
        for (int kk = 0; kk < KSTAGE; kk += 16) {
            unsigned a0[4], a1[4], b0[4], b1[4];
            const int lr = lane & 15;
            const int lc = kk + (lane >> 4) * 8;
            LDSM_X4(a0, &As[buf][wm + lr][lc]);
            LDSM_X4(a1, &As[buf][wm + 16 + lr][lc]);
            LDSM_X4(b0, &Bs[buf][wn + lr][lc]);
            LDSM_X4(b1, &Bs[buf][wn + 16 + lr][lc]);

            MMA_BF16(acc[0][0], a0, b0[0], b0[2]);
            MMA_BF16(acc[0][1], a0, b0[1], b0[3]);
            MMA_BF16(acc[0][2], a0, b1[0], b1[2]);
            MMA_BF16(acc[0][3], a0, b1[1], b1[3]);
            MMA_BF16(acc[1][0], a1, b0[0], b0[2]);
            MMA_BF16(acc[1][1], a1, b0[1], b0[3]);
            MMA_BF16(acc[1][2], a1, b1[0], b1[2]);
            MMA_BF16(acc[1][3], a1, b1[1], b1[3]);
        }
        __syncthreads();
    }

    // write per-block GEMM partials
    float* op = g_part[blk];
    const int g  = lane >> 2;
    const int tt = lane & 3;
#pragma unroll
    for (int mi = 0; mi < 2; ++mi)
#pragma unroll
        for (int nj = 0; nj < 4; ++nj) {
            const int r = wm + mi * 16 + g;
            const int cc = wn + nj * 8 + tt * 2;
            *(float2*)&op[r * 128 + cc]       = make_float2(acc[mi][nj][0], acc[mi][nj][1]);
            *(float2*)&op[(r + 8) * 128 + cc] = make_float2(acc[mi][nj][2], acc[mi][nj][3]);
        }

    // reduce norms over the 8 threads sharing each row
#pragma unroll
    for (int d = 4; d; d >>= 1) {
        x2a += __shfl_down_sync(0xffffffffu, x2a, d, 8);
        x2b += __shfl_down_sync(0xffffffffu, x2b, d, 8);
        y2a += __shfl_down_sync(0xffffffffu, y2a, d, 8);
        y2b += __shfl_down_sync(0xffffffffu, y2b, d, 8);
    }
    if ((t & 7) == 0) {
        g_x2p[blk][row0]      = x2a;
        g_x2p[blk][row0 + 64] = x2b;
        g_y2p[blk][row0]      = y2a;
        g_y2p[blk][row0 + 64] = y2b;
    }
}

// =====================================================================
// Kernel B: reduce split-K partials, assemble C = sqrt(max(x2+y2-2xy,0))
// =====================================================================
__global__ void reduce_kernel()
{
    const int i = blockIdx.x;
    const int j = threadIdx.x;
    float xy = 0.f, x2 = 0.f, y2 = 0.f;
    for (int b = 0; b < NBLK; ++b) {
        xy += g_part[b][i * 128 + j];
        x2 += g_x2p[b][i];
        y2 += g_y2p[b][j];
    }
    const float sq = fmaxf(x2 + y2 - 2.f * xy, 0.f);
    g_C[i * 128 + j] = sqrtf(sq);
}

// =====================================================================
// Kernel C: single-block Sinkhorn.
//   K = exp(C - m); per iteration:
//     S_i = sum_j K_ij * beta_j ;  u_i = REG*(log_a + u_i - m - log S_i); alpha=exp(-u)
//     T_j = sum_i K_ij * alpha_i;  v_j = REG*(log_b + v_j - m - log T_j); beta =exp(-v)
//   out = (sum u + sum v) / 128
// =====================================================================
__global__ void __launch_bounds__(1024, 1)
sinkhorn_kernel(float* __restrict__ out)
{
    extern __shared__ float sm[];
    float* Krow = sm;                     // 128*132
    float* Kcol = Krow + 128 * 132;       // 128*132 (transposed copy)
    float* uu   = Kcol + 128 * 132;       // 128
    float* vv   = uu + 128;
    float* alp  = vv + 128;
    float* bet  = alp + 128;
    float* part = bet + 128;              // 1024
    float* red  = part + 1024;            // 33

    const int tid  = threadIdx.x;
    const int lane = tid & 31;
    const int w    = tid >> 5;

    // load C, find global max
    float cv[16];
    float lm = -3.4e38f;
#pragma unroll
    for (int n = 0; n < 16; ++n) {
        cv[n] = g_C[tid + n * 1024];
        lm = fmaxf(lm, cv[n]);
    }
#pragma unroll
    for (int d = 16; d; d >>= 1) lm = fmaxf(lm, __shfl_xor_sync(0xffffffffu, lm, d));
    if (lane == 0) red[w] = lm;
    __syncthreads();
    if (tid == 0) {
        float mm = red[0];
        for (int q = 1; q < 32; ++q) mm = fmaxf(mm, red[q]);
        red[32] = mm;
    }
    __syncthreads();
    const float m = red[32];

    // build K (row-major and transposed)
#pragma unroll
    for (int n = 0; n < 16; ++n) {
        const int e = tid + n * 1024;
        const int i = e >> 7, j = e & 127;
        const float kv = __expf(cv[n] - m);
        Krow[i * 132 + j] = kv;
        Kcol[j * 132 + i] = kv;
    }
    if (tid < 128) { uu[tid] = 0.f; vv[tid] = 0.f; bet[tid] = 1.f; }
    __syncthreads();

    const int i = tid & 127;      // row (u phase) / col (v phase)
    const int c = tid >> 7;       // 16-wide chunk 0..7
    const float4* Kr4 = (const float4*)(Krow + i * 132 + c * 16);
    const float4* Kc4 = (const float4*)(Kcol + i * 132 + c * 16);
    const float4* b4  = (const float4*)(bet + c * 16);
    const float4* a4  = (const float4*)(alp + c * 16);

    for (int it = 0; it < NUM_SINK; ++it) {
        // ---- u phase ----
        float s = 0.f;
#pragma unroll
        for (int q = 0; q < 4; ++q) {
            const float4 kq = Kr4[q];
            const float4 bq = b4[q];
            s = fmaf(kq.x, bq.x, s); s = fmaf(kq.y, bq.y, s);
            s = fmaf(kq.z, bq.z, s); s = fmaf(kq.w, bq.w, s);
        }
        part[c * 128 + i] = s;
        __syncthreads();
        if (tid < 128) {
            float S = 0.f;
#pragma unroll
            for (int q = 0; q < 8; ++q) S += part[q * 128 + tid];
            const float un = REGW * (LOG_AB + uu[tid] - m - __logf(S));
            uu[tid]  = un;
            alp[tid] = __expf(-un);
        }
        __syncthreads();
        // ---- v phase ----
        float tsum = 0.f;
#pragma unroll
        for (int q = 0; q < 4; ++q) {
            const float4 kq = Kc4[q];
            const float4 aq = a4[q];
            tsum = fmaf(kq.x, aq.x, tsum); tsum = fmaf(kq.y, aq.y, tsum);
            tsum = fmaf(kq.z, aq.z, tsum); tsum = fmaf(kq.w, aq.w, tsum);
        }
        part[c * 128 + i] = tsum;
        __syncthreads();
        if (tid < 128) {
            float T = 0.f;
#pragma unroll
            for (int q = 0; q < 8; ++q) T += part[q * 128 + tid];
            const float vn = REGW * (LOG_AB + vv[tid] - m - __logf(T));
            vv[tid]  = vn;
            bet[tid] = __expf(-vn);
        }
        __syncthreads();
    }

    if (tid < 128) part[tid] = uu[tid] + vv[tid];
    __syncthreads();
    if (tid == 0) {
        float tot = 0.f;
        for (int q = 0; q < 128; ++q) tot += part[q];
        out[0] = tot * (1.0f / 128.0f);
    }
}

// =====================================================================
extern "C" void kernel_launch(void* const* d_in, const int* in_sizes, int n_in,
                              void* d_out, int out_size)
{
    const float* gi = (const float*)d_in[0];   // imgs
    const float* gw = (const float*)d_in[1];   // imgs_w
    const float* gt = (const float*)d_in[2];   // target
    float* out = (float*)d_out;

    const int smem_sink = (128 * 132 * 2 + 128 * 4 + 1024 + 33) * (int)sizeof(float);
    cudaFuncSetAttribute(sinkhorn_kernel,
                         cudaFuncAttributeMaxDynamicSharedMemorySize, smem_sink);

    gemm_kernel<<<NBLK, 512>>>(gi, gw, gt);
    reduce_kernel<<<BSZ, BSZ>>>();
    sinkhorn_kernel<<<1, 1024, smem_sink>>>(out);
}

// round 5
// speedup vs baseline: 1.6339x; 1.6339x over previous
#include <cuda_runtime.h>
#include <cuda_bf16.h>
#include <cstdint>

#define BSZ     128
#define DTOT    196608          // 3*256*256
#define KSTAGE  32
#define CHUNK   1344            // 42 stages of 32 (last block: 12 stages)
#define NBLK    147             // ceil(196608/1344)
#define REGW    0.01f
#define NUM_SINK 10
#define LOG_AB  (-4.852030263919617f)   // log(1/128)

// -------- device scratch (static: no allocations allowed) --------
__device__ float g_part[NBLK][BSZ * BSZ];   // per-block GEMM partials (~9.6 MB)
__device__ float g_x2p[NBLK][BSZ];
__device__ float g_y2p[NBLK][BSZ];
__device__ float g_C[BSZ * BSZ];

__device__ __forceinline__ unsigned smem_u32(const void* p) {
    return (unsigned)__cvta_generic_to_shared(p);
}

__device__ __forceinline__ void cp16(void* dst, const void* src) {
    asm volatile("cp.async.cg.shared.global [%0], [%1], 16;\n"
                 :: "r"(smem_u32(dst)), "l"(src));
}
#define CP_COMMIT() asm volatile("cp.async.commit_group;\n" ::: "memory")
#define CP_WAIT2()  asm volatile("cp.async.wait_group 2;\n" ::: "memory")

#define MMA_BF16(d, A, bx, by)                                                  \
    asm volatile("mma.sync.aligned.m16n8k16.row.col.f32.bf16.bf16.f32 "         \
                 "{%0,%1,%2,%3}, {%4,%5,%6,%7}, {%8,%9}, {%0,%1,%2,%3};"        \
                 : "+f"(d[0]), "+f"(d[1]), "+f"(d[2]), "+f"(d[3])               \
                 : "r"(A[0]), "r"(A[1]), "r"(A[2]), "r"(A[3]), "r"(bx), "r"(by))

#define LDSM_X4(r, p)                                                           \
    asm volatile("ldmatrix.sync.aligned.m8n8.x4.shared.b16 {%0,%1,%2,%3}, [%4];"\
                 : "=r"(r[0]), "=r"(r[1]), "=r"(r[2]), "=r"(r[3])               \
                 : "r"(smem_u32(p)))

// smem layout constants (gemm)
#define RAW_PER_ARR  4096                    // 128 rows * 32 floats
#define RAW_PER_STG  (3 * RAW_PER_ARR)       // 3 arrays
#define RAW_BYTES    (3 * RAW_PER_STG * 4)   // 3 stages = 147456 B
#define GEMM_SMEM    (RAW_BYTES + 2 * 128 * 40 * 2)   // + As/Bs bf16 = 167936 B

// =====================================================================
// Kernel A: split-K bf16 GEMM of Delta @ Target^T, plus fp32 row norms.
// cp.async 3-deep pipeline: raw fp32 tiles staged in smem, converted to
// bf16 (delta computed on the fly) for ldmatrix+mma.
// =====================================================================
__global__ void __launch_bounds__(512, 1)
gemm_kernel(const float* __restrict__ gi,   // imgs
            const float* __restrict__ gw,   // imgs_w
            const float* __restrict__ gt)   // target
{
    extern __shared__ unsigned char smem[];
    float*         raw = (float*)smem;                         // [3][3][4096]
    __nv_bfloat16* As  = (__nv_bfloat16*)(smem + RAW_BYTES);   // [128][40]
    __nv_bfloat16* Bs  = As + 128 * 40;                        // [128][40]

    const int t       = threadIdx.x;
    const int blk     = blockIdx.x;
    const int k0      = blk * CHUNK;
    const int kcount  = min(CHUNK, DTOT - k0);
    const int nstages = kcount / KSTAGE;     // 42 (last block: 12)

    const int lane = t & 31;
    const int warp = t >> 5;
    const int wm   = (warp >> 2) * 32;    // output row base of this warp
    const int wn   = (warp & 3) * 32;     // output col base

    float acc[2][4][4];
#pragma unroll
    for (int a = 0; a < 2; ++a)
#pragma unroll
        for (int b = 0; b < 4; ++b)
#pragma unroll
            for (int r = 0; r < 4; ++r) acc[a][b][r] = 0.f;

    const int row0 = t >> 3;          // 0..63 (convert phase row)
    const int cseg = (t & 7) * 4;     // float offset within 32-wide stage

    // cp.async copy mapping: 1024 16B-chunks per array per stage
    const int ch0   = t * 2;
    const int crow0 = ch0 >> 3;           // rows for the two chunks
    const int ccc0  = (ch0 & 7) * 4;
    const int ch1   = ch0 + 1;
    const int crow1 = ch1 >> 3;
    const int ccc1  = (ch1 & 7) * 4;

    float x2a = 0.f, x2b = 0.f, y2a = 0.f, y2b = 0.f;

    // ---- prologue: issue stages 0,1,2 ----
#pragma unroll
    for (int s = 0; s < 3; ++s) {
        if (s < nstages) {
            float* base = raw + (s % 3) * RAW_PER_STG;
            const size_t g0 = (size_t)crow0 * DTOT + k0 + (size_t)s * KSTAGE + ccc0;
            const size_t g1 = (size_t)crow1 * DTOT + k0 + (size_t)s * KSTAGE + ccc1;
            const int s0 = crow0 * 32 + ccc0;
            const int s1 = crow1 * 32 + ccc1;
            cp16(base + s0,                    gi + g0);
            cp16(base + s1,                    gi + g1);
            cp16(base + RAW_PER_ARR + s0,      gw + g0);
            cp16(base + RAW_PER_ARR + s1,      gw + g1);
            cp16(base + 2 * RAW_PER_ARR + s0,  gt + g0);
            cp16(base + 2 * RAW_PER_ARR + s1,  gt + g1);
        }
        CP_COMMIT();
    }

    for (int s = 0; s < nstages; ++s) {
        CP_WAIT2();
        __syncthreads();   // stage s raw visible to all; prev MMA reads done

        const float* ri = raw + (s % 3) * RAW_PER_STG;
        const float* rw = ri + RAW_PER_ARR;
        const float* rt = ri + 2 * RAW_PER_ARR;

        // convert: delta -> As (bf16), target -> Bs (bf16), accumulate norms
        {
            const int o0 = row0 * 32 + cseg;
            float4 i4 = *(const float4*)(ri + o0);
            float4 w4 = *(const float4*)(rw + o0);
            float4 t4 = *(const float4*)(rt + o0);
            float4 d;
            d.x = w4.x - i4.x; d.y = w4.y - i4.y;
            d.z = w4.z - i4.z; d.w = w4.w - i4.w;
            x2a += d.x*d.x + d.y*d.y + d.z*d.z + d.w*d.w;
            y2a += t4.x*t4.x + t4.y*t4.y + t4.z*t4.z + t4.w*t4.w;
            *(__nv_bfloat162*)&As[row0 * 40 + cseg + 0] = __float22bfloat162_rn(make_float2(d.x, d.y));
            *(__nv_bfloat162*)&As[row0 * 40 + cseg + 2] = __float22bfloat162_rn(make_float2(d.z, d.w));
            *(__nv_bfloat162*)&Bs[row0 * 40 + cseg + 0] = __float22bfloat162_rn(make_float2(t4.x, t4.y));
            *(__nv_bfloat162*)&Bs[row0 * 40 + cseg + 2] = __float22bfloat162_rn(make_float2(t4.z, t4.w));
        }
        {
            const int o1 = (row0 + 64) * 32 + cseg;
            float4 i4 = *(const float4*)(ri + o1);
            float4 w4 = *(const float4*)(rw + o1);
            float4 t4 = *(const float4*)(rt + o1);
            float4 d;
            d.x = w4.x - i4.x; d.y = w4.y - i4.y;
            d.z = w4.z - i4.z; d.w = w4.w - i4.w;
            x2b += d.x*d.x + d.y*d.y + d.z*d.z + d.w*d.w;
            y2b += t4.x*t4.x + t4.y*t4.y + t4.z*t4.z + t4.w*t4.w;
            *(__nv_bfloat162*)&As[(row0 + 64) * 40 + cseg + 0] = __float22bfloat162_rn(make_float2(d.x, d.y));
            *(__nv_bfloat162*)&As[(row0 + 64) * 40 + cseg + 2] = __float22bfloat162_rn(make_float2(d.z, d.w));
            *(__nv_bfloat162*)&Bs[(row0 + 64) * 40 + cseg + 0] = __float22bfloat162_rn(make_float2(t4.x, t4.y));
            *(__nv_bfloat162*)&Bs[(row0 + 64) * 40 + cseg + 2] = __float22bfloat162_rn(make_float2(t4.z, t4.w));
        }

        __syncthreads();   // bf16 tiles ready; raw[s%3] free for refill

        // issue stage s+3 (reuses raw buffer s%3, now fully consumed)
        if (s + 3 < nstages) {
            float* base = raw + (s % 3) * RAW_PER_STG;
            const size_t adv = (size_t)(s + 3) * KSTAGE;
            const size_t g0 = (size_t)crow0 * DTOT + k0 + adv + ccc0;
            const size_t g1 = (size_t)crow1 * DTOT + k0 + adv + ccc1;
            const int s0 = crow0 * 32 + ccc0;
            const int s1 = crow1 * 32 + ccc1;
            cp16(base + s0,                    gi + g0);
            cp16(base + s1,                    gi + g1);
            cp16(base + RAW_PER_ARR + s0,      gw + g0);
            cp16(base + RAW_PER_ARR + s1,      gw + g1);
            cp16(base + 2 * RAW_PER_ARR + s0,  gt + g0);
            cp16(base + 2 * RAW_PER_ARR + s1,  gt + g1);
        }
        CP_COMMIT();   // always commit (possibly empty) to keep group math uniform

#pragma unroll
        for (int kk = 0; kk < KSTAGE; kk += 16) {
            unsigned a0[4], a1[4], b0[4], b1[4];
            const int lr = lane & 15;
            const int lc = kk + (lane >> 4) * 8;
            LDSM_X4(a0, &As[(wm + lr) * 40 + lc]);
            LDSM_X4(a1, &As[(wm + 16 + lr) * 40 + lc]);
            LDSM_X4(b0, &Bs[(wn + lr) * 40 + lc]);
            LDSM_X4(b1, &Bs[(wn + 16 + lr) * 40 + lc]);

            MMA_BF16(acc[0][0], a0, b0[0], b0[2]);
            MMA_BF16(acc[0][1], a0, b0[1], b0[3]);
            MMA_BF16(acc[0][2], a0, b1[0], b1[2]);
            MMA_BF16(acc[0][3], a0, b1[1], b1[3]);
            MMA_BF16(acc[1][0], a1, b0[0], b0[2]);
            MMA_BF16(acc[1][1], a1, b0[1], b0[3]);
            MMA_BF16(acc[1][2], a1, b1[0], b1[2]);
            MMA_BF16(acc[1][3], a1, b1[1], b1[3]);
        }
        __syncthreads();   // all ldmatrix reads done before next convert overwrites
    }

    // write per-block GEMM partials
    float* op = g_part[blk];
    const int g  = lane >> 2;
    const int tt = lane & 3;
#pragma unroll
    for (int mi = 0; mi < 2; ++mi)
#pragma unroll
        for (int nj = 0; nj < 4; ++nj) {
            const int r  = wm + mi * 16 + g;
            const int cc = wn + nj * 8 + tt * 2;
            *(float2*)&op[r * 128 + cc]       = make_float2(acc[mi][nj][0], acc[mi][nj][1]);
            *(float2*)&op[(r + 8) * 128 + cc] = make_float2(acc[mi][nj][2], acc[mi][nj][3]);
        }

    // reduce norms over the 8 threads sharing each row
#pragma unroll
    for (int d = 4; d; d >>= 1) {
        x2a += __shfl_down_sync(0xffffffffu, x2a, d, 8);
        x2b += __shfl_down_sync(0xffffffffu, x2b, d, 8);
        y2a += __shfl_down_sync(0xffffffffu, y2a, d, 8);
        y2b += __shfl_down_sync(0xffffffffu, y2b, d, 8);
    }
    if ((t & 7) == 0) {
        g_x2p[blk][row0]      = x2a;
        g_x2p[blk][row0 + 64] = x2b;
        g_y2p[blk][row0]      = y2a;
        g_y2p[blk][row0 + 64] = y2b;
    }
}

// =====================================================================
// Kernel B: reduce split-K partials, assemble C = sqrt(max(x2+y2-2xy,0))
// =====================================================================
__global__ void reduce_kernel()
{
    const int i = blockIdx.x;
    const int j = threadIdx.x;
    float xy = 0.f, x2 = 0.f, y2 = 0.f;
#pragma unroll 7
    for (int b = 0; b < NBLK; ++b) {
        xy += g_part[b][i * 128 + j];
        x2 += g_x2p[b][i];
        y2 += g_y2p[b][j];
    }
    const float sq = fmaxf(x2 + y2 - 2.f * xy, 0.f);
    g_C[i * 128 + j] = sqrtf(sq);
}

// =====================================================================
// Kernel C: single-block Sinkhorn, 128 threads (row-per-thread matvecs).
//   K = exp(C - m); per iteration:
//     S_i = sum_j K_ij * beta_j ;  u_i = REG*(log_a + u_i - m - log S_i); alpha=exp(-u)
//     T_j = sum_i K_ij * alpha_i;  v_j = REG*(log_b + v_j - m - log T_j); beta =exp(-v)
//   out = (sum u + sum v) / 128
// Map contracts at ~2*REG=0.02 per iter -> 10 iterations is far past fp32 eps.
// =====================================================================
__global__ void __launch_bounds__(128, 1)
sinkhorn_kernel(float* __restrict__ out)
{
    extern __shared__ float sm[];
    float* Krow = sm;                     // 128*132
    float* Kcol = Krow + 128 * 132;       // 128*132 (transposed copy)
    float* uu   = Kcol + 128 * 132;       // 128
    float* vv   = uu + 128;
    float* alp  = vv + 128;
    float* bet  = alp + 128;
    float* red  = bet + 128;              // 8

    const int tid  = threadIdx.x;
    const int lane = tid & 31;
    const int w    = tid >> 5;

    const float4* Crow4 = (const float4*)(g_C + tid * 128);

    // pass 1: global max of C
    float lm = -3.4e38f;
#pragma unroll
    for (int q = 0; q < 32; ++q) {
        const float4 c = Crow4[q];
        lm = fmaxf(lm, fmaxf(fmaxf(c.x, c.y), fmaxf(c.z, c.w)));
    }
#pragma unroll
    for (int d = 16; d; d >>= 1) lm = fmaxf(lm, __shfl_xor_sync(0xffffffffu, lm, d));
    if (lane == 0) red[w] = lm;
    __syncthreads();
    if (tid == 0) red[4] = fmaxf(fmaxf(red[0], red[1]), fmaxf(red[2], red[3]));
    __syncthreads();
    const float m = red[4];

    // pass 2: build K row-major + transposed copy
#pragma unroll
    for (int q = 0; q < 32; ++q) {
        const float4 c = Crow4[q];
        const float k0 = __expf(c.x - m);
        const float k1 = __expf(c.y - m);
        const float k2 = __expf(c.z - m);
        const float k3 = __expf(c.w - m);
        *(float4*)&Krow[tid * 132 + q * 4] = make_float4(k0, k1, k2, k3);
        Kcol[(q * 4 + 0) * 132 + tid] = k0;
        Kcol[(q * 4 + 1) * 132 + tid] = k1;
        Kcol[(q * 4 + 2) * 132 + tid] = k2;
        Kcol[(q * 4 + 3) * 132 + tid] = k3;
    }
    uu[tid] = 0.f; vv[tid] = 0.f; bet[tid] = 1.f;
    __syncthreads();

    const float4* Kr4 = (const float4*)(Krow + tid * 132);
    const float4* Kc4 = (const float4*)(Kcol + tid * 132);
    const float4* b4  = (const float4*)bet;
    const float4* a4  = (const float4*)alp;

    for (int it = 0; it < NUM_SINK; ++it) {
        // ---- u phase: S_i = K[i,:] . beta ----
        float s = 0.f;
#pragma unroll
        for (int q = 0; q < 32; ++q) {
            const float4 k = Kr4[q];
            const float4 b = b4[q];
            s = fmaf(k.x, b.x, s); s = fmaf(k.y, b.y, s);
            s = fmaf(k.z, b.z, s); s = fmaf(k.w, b.w, s);
        }
        const float un = REGW * (LOG_AB + uu[tid] - m - __logf(s));
        uu[tid]  = un;
        alp[tid] = __expf(-un);
        __syncthreads();

        // ---- v phase: T_j = K[:,j] . alpha ----
        float ts = 0.f;
#pragma unroll
        for (int q = 0; q < 32; ++q) {
            const float4 k = Kc4[q];
            const float4 a = a4[q];
            ts = fmaf(k.x, a.x, ts); ts = fmaf(k.y, a.y, ts);
            ts = fmaf(k.z, a.z, ts); ts = fmaf(k.w, a.w, ts);
        }
        const float vn = REGW * (LOG_AB + vv[tid] - m - __logf(ts));
        vv[tid]  = vn;
        bet[tid] = __expf(-vn);
        __syncthreads();
    }

    // out = (sum u + sum v) / 128
    float val = uu[tid] + vv[tid];
#pragma unroll
    for (int d = 16; d; d >>= 1) val += __shfl_xor_sync(0xffffffffu, val, d);
    if (lane == 0) red[w] = val;
    __syncthreads();
    if (tid == 0)
        out[0] = (red[0] + red[1] + red[2] + red[3]) * (1.0f / 128.0f);
}

// =====================================================================
extern "C" void kernel_launch(void* const* d_in, const int* in_sizes, int n_in,
                              void* d_out, int out_size)
{
    const float* gi = (const float*)d_in[0];   // imgs
    const float* gw = (const float*)d_in[1];   // imgs_w
    const float* gt = (const float*)d_in[2];   // target
    float* out = (float*)d_out;

    cudaFuncSetAttribute(gemm_kernel,
                         cudaFuncAttributeMaxDynamicSharedMemorySize, GEMM_SMEM);
    const int smem_sink = (2 * 128 * 132 + 4 * 128 + 8) * (int)sizeof(float);
    cudaFuncSetAttribute(sinkhorn_kernel,
                         cudaFuncAttributeMaxDynamicSharedMemorySize, smem_sink);

    gemm_kernel<<<NBLK, 512, GEMM_SMEM>>>(gi, gw, gt);
    reduce_kernel<<<BSZ, BSZ>>>();
    sinkhorn_kernel<<<1, 128, smem_sink>>>(out);
}